// round 11
// baseline (speedup 1.0000x reference)
#include <cuda_runtime.h>
#include <math.h>

#define NMAT_X 32768
#define C_CLS  128
#define NDIM   64
#define NSQ    4096          // 64*64
#define PITCH  65            // smem pitch for A (odd -> conflict-free columns)
#define PITCHV 68            // smem pitch for Vt (16B-aligned float4 rows)
#define MAXSWEEP 13

// ---- scratch (device globals; no runtime allocation allowed) ----
__device__ float g_logX[134217728];   // 32768 * 4096  (512 MB)
__device__ float g_logP[C_CLS * NSQ];
__device__ float g_Asym[C_CLS * NSQ];
__device__ float g_offs[C_CLS];

// ---- packed f32x2 helpers (Blackwell FFMA2 path) ----
typedef unsigned long long u64;
__device__ __forceinline__ u64 pk2(float lo, float hi) {
    u64 r;
    asm("mov.b64 %0, {%1, %2};" : "=l"(r)
        : "r"(__float_as_uint(lo)), "r"(__float_as_uint(hi)));
    return r;
}
__device__ __forceinline__ void upk2(u64 v, float& lo, float& hi) {
    unsigned int l, h;
    asm("mov.b64 {%0, %1}, %2;" : "=r"(l), "=r"(h) : "l"(v));
    lo = __uint_as_float(l); hi = __uint_as_float(h);
}
__device__ __forceinline__ u64 mul2_(u64 a, u64 b) {
    u64 r; asm("mul.rn.f32x2 %0, %1, %2;" : "=l"(r) : "l"(a), "l"(b)); return r;
}
__device__ __forceinline__ u64 fma2_(u64 a, u64 b, u64 c) {
    u64 r; asm("fma.rn.f32x2 %0, %1, %2, %3;" : "=l"(r) : "l"(a), "l"(b), "l"(c)); return r;
}

// =====================================================================
// A_sym = tril(A,-1) + tril(A,-1)^T + diag(A)
// =====================================================================
__global__ __launch_bounds__(256) void make_asym_k(const float* __restrict__ A,
                                                   float* __restrict__ S) {
    int c = blockIdx.x;
    const float* Ac = A + (size_t)c * NSQ;
    float* Sc = S + (size_t)c * NSQ;
    for (int t = threadIdx.x; t < NSQ; t += 256) {
        int i = t >> 6, j = t & 63;
        float v;
        if (i == j)      v = Ac[t];
        else if (i > j)  v = Ac[i * 64 + j];
        else             v = Ac[j * 64 + i];
        Sc[t] = v;
    }
}

// =====================================================================
// Batched Jacobi eigensolver + logm reconstruction.
// One block (256 threads) per 64x64 SPD matrix.
// Canonical lower-triangle storage; 496 strictly-lower pair-blocks,
// TWO tasks per thread packed into f32x2 lanes (FFMA2). Analytic
// diagonal update in phase 1. Vt transposed, packed-f32x2 updates.
// =====================================================================
__device__ __forceinline__ void tourney_pair(int r, int i, int* p, int* q) {
    if (i == 0) { *p = 0; *q = 1 + r; }
    else {
        *p = 1 + (r + i) % 63;
        *q = 1 + (r - i + 63) % 63;
    }
}

__device__ __forceinline__ void decode_tri(int t, int* rp, int* cp) {
    // t in [0,496): rp in [1,31], cp in [0,rp), t = rp*(rp-1)/2 + cp
    int r = (int)((1.f + sqrtf(8.f * (float)t + 1.f)) * 0.5f);
    while (r * (r - 1) / 2 > t) --r;
    while ((r + 1) * r / 2 <= t) ++r;
    *rp = r;
    *cp = t - r * (r - 1) / 2;
}

__global__ __launch_bounds__(256, 6) void jacobi_logm_k(const float* __restrict__ in,
                                                        float* __restrict__ out) {
    __shared__ float As[NDIM * PITCH];
    __shared__ __align__(16) float Vt[NDIM * PITCHV];
    __shared__ float2 cssn[32];
    __shared__ int    pqA[32];
    __shared__ float wsum[8];
    __shared__ float fro2v;
    __shared__ int   convflag;
    __shared__ float ev[64];

    const int tid = threadIdx.x;
    const size_t m = blockIdx.x;
    const float* Xm = in + m * (size_t)NSQ;

    // ---- per-thread canonical block-task assignment (fixed all rounds) ----
    int rp1, cp1, rp2, cp2;
    const bool has2 = (tid < 240);
    decode_tri(tid, &rp1, &cp1);
    if (has2) decode_tri(tid + 256, &rp2, &cp2);
    else      { rp2 = rp1; cp2 = cp1; }   // hi lane mirrors lo; stores guarded

    // ---- load A, init Vt = I, accumulate ||A||_F^2 ----
    float part = 0.f;
    for (int t = tid; t < NSQ; t += 256) {
        int i = t >> 6, j = t & 63;
        float v = Xm[t];
        As[i * PITCH + j] = v;
        Vt[i * PITCHV + j] = (i == j) ? 1.f : 0.f;
        part += v * v;
    }
    #pragma unroll
    for (int o = 16; o; o >>= 1) part += __shfl_down_sync(0xffffffffu, part, o);
    if ((tid & 31) == 0) wsum[tid >> 5] = part;
    __syncthreads();
    if (tid == 0) {
        float s = 0.f;
        #pragma unroll
        for (int w = 0; w < 8; ++w) s += wsum[w];
        fro2v = s;
        convflag = 0;
    }
    __syncthreads();

    // ---- Jacobi sweeps ----
    for (int sweep = 0; sweep < MAXSWEEP; ++sweep) {
        if (sweep >= 4) {
            // off-diagonal norm: strictly-lower canonical x2
            float po = 0.f;
            for (int t = tid; t < NSQ; t += 256) {
                int i = t >> 6, j = t & 63;
                if (i > j) { float v = As[i * PITCH + j]; po += v * v; }
            }
            #pragma unroll
            for (int o = 16; o; o >>= 1) po += __shfl_down_sync(0xffffffffu, po, o);
            if ((tid & 31) == 0) wsum[tid >> 5] = po;
            __syncthreads();
            if (tid == 0) {
                float s = 0.f;
                #pragma unroll
                for (int w = 0; w < 8; ++w) s += wsum[w];
                convflag = (2.f * s <= 1e-10f * fro2v) ? 1 : 0;
            }
            __syncthreads();
            if (convflag) break;
        }

        for (int r = 0; r < 63; ++r) {
            // --- phase 1: 32 rotation params + analytic diagonal update ---
            if (tid < 32) {
                int p, q;
                tourney_pair(r, tid, &p, &q);
                pqA[tid] = p | (q << 8);
                const int dpa = p * PITCH + p;
                const int dqa = q * PITCH + q;
                const int oqa = max(p, q) * PITCH + min(p, q);
                float app = As[dpa];
                float aqq = As[dqa];
                float apq = As[oqa];
                float c = 1.f, s = 0.f, tg = 0.f;
                if (fabsf(apq) > 1e-30f) {
                    float tau = (aqq - app) / (2.0f * apq);
                    tg = 1.0f / (fabsf(tau) + sqrtf(1.0f + tau * tau));
                    if (tau < 0.f) tg = -tg;
                    c = rsqrtf(1.f + tg * tg);
                    s = tg * c;
                }
                cssn[tid] = make_float2(c, s);
                float dpq = tg * apq;
                As[dpa] = app - dpq;
                As[dqa] = aqq + dpq;
                As[oqa] = 0.f;
            }
            __syncthreads();

            // --- phase 2a: 496 strictly-lower 2x2 blocks, 2 tasks packed ---
            {
                // row-pair params (lo = task1, hi = task2)
                const int pqr1 = pqA[rp1], pqr2 = pqA[rp2];
                const int P1 = pqr1 & 255, Q1 = pqr1 >> 8;
                const int P1b = pqr2 & 255, Q1b = pqr2 >> 8;
                const float2 cr1 = cssn[rp1], cr2 = cssn[rp2];
                // col-pair params
                const int pqc1 = pqA[cp1], pqc2 = pqA[cp2];
                const int P2 = pqc1 & 255, Q2 = pqc1 >> 8;
                const int P2b = pqc2 & 255, Q2b = pqc2 >> 8;
                const float2 cc1 = cssn[cp1], cc2 = cssn[cp2];

                const u64 c1p  = pk2(cr1.x, cr2.x);
                const u64 s1p  = pk2(cr1.y, cr2.y);
                const u64 ns1p = pk2(-cr1.y, -cr2.y);
                const u64 c2p  = pk2(cc1.x, cc2.x);
                const u64 s2p  = pk2(cc1.y, cc2.y);
                const u64 ns2p = pk2(-cc1.y, -cc2.y);

                // canonical addresses (max-row, min-col)
                const int a00A = max(P1, P2)  * PITCH + min(P1, P2);
                const int a01A = max(P1, Q2)  * PITCH + min(P1, Q2);
                const int a10A = max(Q1, P2)  * PITCH + min(Q1, P2);
                const int a11A = max(Q1, Q2)  * PITCH + min(Q1, Q2);
                const int a00B = max(P1b, P2b) * PITCH + min(P1b, P2b);
                const int a01B = max(P1b, Q2b) * PITCH + min(P1b, Q2b);
                const int a10B = max(Q1b, P2b) * PITCH + min(Q1b, P2b);
                const int a11B = max(Q1b, Q2b) * PITCH + min(Q1b, Q2b);

                const float x00 = As[a00A], x01 = As[a01A];
                const float x10 = As[a10A], x11 = As[a11A];
                const float y00 = As[a00B], y01 = As[a01B];
                const float y10 = As[a10B], y11 = As[a11B];

                const u64 e00 = pk2(x00, y00), e01 = pk2(x01, y01);
                const u64 e10 = pk2(x10, y10), e11 = pk2(x11, y11);

                const u64 t00 = fma2_(c1p, e00, mul2_(ns1p, e10));
                const u64 t01 = fma2_(c1p, e01, mul2_(ns1p, e11));
                const u64 t10 = fma2_(s1p, e00, mul2_(c1p,  e10));
                const u64 t11 = fma2_(s1p, e01, mul2_(c1p,  e11));

                const u64 n00 = fma2_(c2p, t00, mul2_(ns2p, t01));
                const u64 n01 = fma2_(s2p, t00, mul2_(c2p,  t01));
                const u64 n10 = fma2_(c2p, t10, mul2_(ns2p, t11));
                const u64 n11 = fma2_(s2p, t10, mul2_(c2p,  t11));

                float lo, hi;
                upk2(n00, lo, hi); As[a00A] = lo; if (has2) As[a00B] = hi;
                upk2(n01, lo, hi); As[a01A] = lo; if (has2) As[a01B] = hi;
                upk2(n10, lo, hi); As[a10A] = lo; if (has2) As[a10B] = hi;
                upk2(n11, lo, hi); As[a11A] = lo; if (has2) As[a11B] = hi;
            }
            // --- phase 2b: Vt rows p,q <- rotation (packed f32x2) ---
            {
                const int pi = tid >> 3;
                const int pqv = pqA[pi];
                const int p = pqv & 255, q = pqv >> 8;
                const float2 cs = cssn[pi];
                const u64 cp  = pk2(cs.x,  cs.x);
                const u64 sp  = pk2(cs.y,  cs.y);
                const u64 nsp = pk2(-cs.y, -cs.y);
                const int rb = (tid & 7) * 8;
                ulonglong2* vp = reinterpret_cast<ulonglong2*>(&Vt[p * PITCHV + rb]);
                ulonglong2* vq = reinterpret_cast<ulonglong2*>(&Vt[q * PITCHV + rb]);
                #pragma unroll
                for (int h = 0; h < 2; ++h) {
                    ulonglong2 a = vp[h], b = vq[h];
                    ulonglong2 np, nq;
                    np.x = fma2_(cp, a.x, mul2_(nsp, b.x));
                    np.y = fma2_(cp, a.y, mul2_(nsp, b.y));
                    nq.x = fma2_(sp, a.x, mul2_(cp, b.x));
                    nq.y = fma2_(sp, a.y, mul2_(cp, b.y));
                    vp[h] = np; vq[h] = nq;
                }
            }
            __syncthreads();
        }
    }

    // ---- eigenvalue logs ----
    if (tid < 64) ev[tid] = logf(fmaxf(As[tid * PITCH + tid], 1e-12f));
    __syncthreads();

    // ---- logX[i][j] = sum_k (Vt[k][i]*ev[k]) * Vt[k][j]  (fused W) ----
    {
        const int bi = tid >> 4;   // 0..15
        const int bj = tid & 15;   // 0..15
        float acc[4][4];
        #pragma unroll
        for (int u = 0; u < 4; ++u)
            #pragma unroll
            for (int v = 0; v < 4; ++v) acc[u][v] = 0.f;
        for (int k = 0; k < 64; ++k) {
            const float evk = ev[k];
            float4 a = *reinterpret_cast<const float4*>(&Vt[k * PITCHV + 4 * bi]);
            float4 b = *reinterpret_cast<const float4*>(&Vt[k * PITCHV + 4 * bj]);
            float wa[4] = {a.x * evk, a.y * evk, a.z * evk, a.w * evk};
            float vb[4] = {b.x, b.y, b.z, b.w};
            #pragma unroll
            for (int u = 0; u < 4; ++u)
                #pragma unroll
                for (int v = 0; v < 4; ++v) acc[u][v] += wa[u] * vb[v];
        }
        float* outm = out + m * (size_t)NSQ;
        #pragma unroll
        for (int u = 0; u < 4; ++u) {
            float4 o = make_float4(acc[u][0], acc[u][1], acc[u][2], acc[u][3]);
            *reinterpret_cast<float4*>(&outm[(4 * bi + u) * 64 + 4 * bj]) = o;
        }
    }
}

// =====================================================================
// offs[c] = <logP_c, Asym_c>
// =====================================================================
__global__ __launch_bounds__(256) void make_offs_k(const float* __restrict__ LP,
                                                   const float* __restrict__ S,
                                                   float* __restrict__ offs) {
    __shared__ float ws[8];
    int c = blockIdx.x;
    float part = 0.f;
    for (int t = threadIdx.x; t < NSQ; t += 256)
        part += LP[(size_t)c * NSQ + t] * S[(size_t)c * NSQ + t];
    #pragma unroll
    for (int o = 16; o; o >>= 1) part += __shfl_down_sync(0xffffffffu, part, o);
    if ((threadIdx.x & 31) == 0) ws[threadIdx.x >> 5] = part;
    __syncthreads();
    if (threadIdx.x == 0) {
        float s = 0.f;
        #pragma unroll
        for (int w = 0; w < 8; ++w) s += ws[w];
        offs[c] = s;
    }
}

// =====================================================================
// out[n,c] = sum_k logX[n,k] * Asym[c,k] - offs[c]
// Tile: 128 n-rows x 128 classes per block, 256 threads, 8x8 per thread
// =====================================================================
__global__ __launch_bounds__(256) void logits_gemm_k(const float* __restrict__ LX,
                                                     const float* __restrict__ B,
                                                     const float* __restrict__ offs,
                                                     float* __restrict__ out) {
    __shared__ float Xs[128][33];
    __shared__ float Bs[128][33];
    const int tid = threadIdx.x;
    const int n0 = blockIdx.x * 128;
    const int ti = tid >> 4;   // 0..15
    const int tj = tid & 15;   // 0..15

    float acc[8][8];
    #pragma unroll
    for (int u = 0; u < 8; ++u)
        #pragma unroll
        for (int v = 0; v < 8; ++v) acc[u][v] = 0.f;

    for (int k0 = 0; k0 < NSQ; k0 += 32) {
        #pragma unroll
        for (int it = 0; it < 4; ++it) {
            int f = tid + it * 256;          // 0..1023
            int row = f >> 3;
            int c4 = (f & 7) * 4;
            float4 x = *reinterpret_cast<const float4*>(
                &LX[(size_t)(n0 + row) * NSQ + k0 + c4]);
            Xs[row][c4] = x.x; Xs[row][c4 + 1] = x.y;
            Xs[row][c4 + 2] = x.z; Xs[row][c4 + 3] = x.w;
            float4 b = *reinterpret_cast<const float4*>(
                &B[(size_t)row * NSQ + k0 + c4]);
            Bs[row][c4] = b.x; Bs[row][c4 + 1] = b.y;
            Bs[row][c4 + 2] = b.z; Bs[row][c4 + 3] = b.w;
        }
        __syncthreads();

        #pragma unroll 4
        for (int kk = 0; kk < 32; ++kk) {
            float xr[8], bc[8];
            #pragma unroll
            for (int u = 0; u < 8; ++u) xr[u] = Xs[ti + 16 * u][kk];
            #pragma unroll
            for (int v = 0; v < 8; ++v) bc[v] = Bs[tj + 16 * v][kk];
            #pragma unroll
            for (int u = 0; u < 8; ++u)
                #pragma unroll
                for (int v = 0; v < 8; ++v) acc[u][v] += xr[u] * bc[v];
        }
        __syncthreads();
    }

    float offv[8];
    #pragma unroll
    for (int v = 0; v < 8; ++v) offv[v] = offs[tj + 16 * v];
    #pragma unroll
    for (int u = 0; u < 8; ++u) {
        size_t rowoff = (size_t)(n0 + ti + 16 * u) * C_CLS;
        #pragma unroll
        for (int v = 0; v < 8; ++v)
            out[rowoff + tj + 16 * v] = acc[u][v] - offv[v];
    }
}

// =====================================================================
extern "C" void kernel_launch(void* const* d_in, const int* in_sizes, int n_in,
                              void* d_out, int out_size) {
    // inputs in metadata order: X (32768*4096), P (128*4096), A (128*4096)
    const float* X = (const float*)d_in[0];
    const float* P = (const float*)d_in[1];
    const float* A = (const float*)d_in[2];
    if (n_in == 3) {
        int xi = 0;
        for (int i = 1; i < 3; ++i) if (in_sizes[i] > in_sizes[xi]) xi = i;
        if (xi != 0) {
            const float* ins[3] = {(const float*)d_in[0], (const float*)d_in[1],
                                   (const float*)d_in[2]};
            X = ins[xi];
            int k = 0;
            const float* rest[2];
            for (int i = 0; i < 3; ++i) if (i != xi) rest[k++] = ins[i];
            P = rest[0]; A = rest[1];
        }
    }
    float* out = (float*)d_out;

    float *p_logX = nullptr, *p_logP = nullptr, *p_Asym = nullptr, *p_offs = nullptr;
    cudaGetSymbolAddress((void**)&p_logX, g_logX);
    cudaGetSymbolAddress((void**)&p_logP, g_logP);
    cudaGetSymbolAddress((void**)&p_Asym, g_Asym);
    cudaGetSymbolAddress((void**)&p_offs, g_offs);

    make_asym_k<<<C_CLS, 256>>>(A, p_Asym);
    jacobi_logm_k<<<C_CLS, 256>>>(P, p_logP);
    jacobi_logm_k<<<NMAT_X, 256>>>(X, p_logX);
    make_offs_k<<<C_CLS, 256>>>(p_logP, p_Asym, p_offs);
    logits_gemm_k<<<NMAT_X / 128, 256>>>(p_logX, p_Asym, p_offs, out);
}

// round 12
// speedup vs baseline: 1.0824x; 1.0824x over previous
#include <cuda_runtime.h>
#include <math.h>

#define NMAT_X 32768
#define C_CLS  128
#define NDIM   64
#define NSQ    4096          // 64*64
#define PITCH  65            // smem pitch for A (odd -> conflict-free columns)
#define PITCHV 68            // smem pitch for Vt (16B-aligned float4 rows)
#define MAXSWEEP 13

// ---- scratch (device globals; no runtime allocation allowed) ----
__device__ float g_logX[134217728];   // 32768 * 4096  (512 MB)
__device__ float g_logP[C_CLS * NSQ];
__device__ float g_Asym[C_CLS * NSQ];
__device__ float g_offs[C_CLS];

// =====================================================================
// A_sym = tril(A,-1) + tril(A,-1)^T + diag(A)
// =====================================================================
__global__ __launch_bounds__(256) void make_asym_k(const float* __restrict__ A,
                                                   float* __restrict__ S) {
    int c = blockIdx.x;
    const float* Ac = A + (size_t)c * NSQ;
    float* Sc = S + (size_t)c * NSQ;
    for (int t = threadIdx.x; t < NSQ; t += 256) {
        int i = t >> 6, j = t & 63;
        float v;
        if (i == j)      v = Ac[t];
        else if (i > j)  v = Ac[i * 64 + j];
        else             v = Ac[j * 64 + i];
        Sc[t] = v;
    }
}

// =====================================================================
// Batched Jacobi eigensolver + logm reconstruction.
// One block (256 threads) per 64x64 SPD matrix.
// Canonical lower-triangle storage; analytic diagonal update in phase 1.
// SOFTWARE-PIPELINED: rotation params double-buffered; the V-update of
// round r-1 runs concurrently with phase 1 of round r (disjoint state:
// phase 1 touches As + buf[r&1]; deferred 2b touches Vt + buf[(r-1)&1]).
// Work and operand order on V identical to R9 -> bit-exact.
// =====================================================================
__device__ __forceinline__ void tourney_pair(int r, int i, int* p, int* q) {
    if (i == 0) { *p = 0; *q = 1 + r; }
    else {
        *p = 1 + (r + i) % 63;
        *q = 1 + (r - i + 63) % 63;
    }
}

__device__ __forceinline__ void decode_tri(int t, int* rp, int* cp) {
    // t in [0,496): rp in [1,31], cp in [0,rp), t = rp*(rp-1)/2 + cp
    int r = (int)((1.f + sqrtf(8.f * (float)t + 1.f)) * 0.5f);
    while (r * (r - 1) / 2 > t) --r;
    while ((r + 1) * r / 2 <= t) ++r;
    *rp = r;
    *cp = t - r * (r - 1) / 2;
}

__global__ __launch_bounds__(256, 6) void jacobi_logm_k(const float* __restrict__ in,
                                                        float* __restrict__ out) {
    __shared__ float As[NDIM * PITCH];
    __shared__ __align__(16) float Vt[NDIM * PITCHV];
    __shared__ float2 cssn[2][32];
    __shared__ int    pqA[2][32];
    __shared__ float wsum[8];
    __shared__ float fro2v;
    __shared__ int   convflag;
    __shared__ float ev[64];

    const int tid = threadIdx.x;
    const size_t m = blockIdx.x;
    const float* Xm = in + m * (size_t)NSQ;

    // ---- per-thread canonical block-task assignment (fixed all rounds) ----
    int rp1, cp1, rp2 = -1, cp2 = -1;
    decode_tri(tid, &rp1, &cp1);
    if (tid < 240) decode_tri(tid + 256, &rp2, &cp2);

    // phase-2b static assignment
    const int pi2b = tid >> 3;
    const int rb2b = (tid & 7) * 8;

    // ---- load A, init Vt = I, accumulate ||A||_F^2 ----
    float part = 0.f;
    for (int t = tid; t < NSQ; t += 256) {
        int i = t >> 6, j = t & 63;
        float v = Xm[t];
        As[i * PITCH + j] = v;
        Vt[i * PITCHV + j] = (i == j) ? 1.f : 0.f;
        part += v * v;
    }
    #pragma unroll
    for (int o = 16; o; o >>= 1) part += __shfl_down_sync(0xffffffffu, part, o);
    if ((tid & 31) == 0) wsum[tid >> 5] = part;
    __syncthreads();
    if (tid == 0) {
        float s = 0.f;
        #pragma unroll
        for (int w = 0; w < 8; ++w) s += wsum[w];
        fro2v = s;
        convflag = 0;
    }
    __syncthreads();

    // ---- Jacobi sweeps ----
    for (int sweep = 0; sweep < MAXSWEEP; ++sweep) {
        if (sweep >= 4) {
            // off-diagonal norm: strictly-lower canonical x2 (As only; any
            // pending V-update was flushed at the previous sweep's end)
            float po = 0.f;
            for (int t = tid; t < NSQ; t += 256) {
                int i = t >> 6, j = t & 63;
                if (i > j) { float v = As[i * PITCH + j]; po += v * v; }
            }
            #pragma unroll
            for (int o = 16; o; o >>= 1) po += __shfl_down_sync(0xffffffffu, po, o);
            if ((tid & 31) == 0) wsum[tid >> 5] = po;
            __syncthreads();
            if (tid == 0) {
                float s = 0.f;
                #pragma unroll
                for (int w = 0; w < 8; ++w) s += wsum[w];
                convflag = (2.f * s <= 1e-10f * fro2v) ? 1 : 0;
            }
            __syncthreads();
            if (convflag) break;
        }

        for (int r = 0; r < 63; ++r) {
            const int cur = r & 1;
            const int prv = cur ^ 1;

            // --- S1a: phase 1 (warp 0): params(r) + analytic diag update ---
            if (tid < 32) {
                int p, q;
                tourney_pair(r, tid, &p, &q);
                pqA[cur][tid] = p | (q << 8);
                const int dpa = p * PITCH + p;
                const int dqa = q * PITCH + q;
                const int oqa = max(p, q) * PITCH + min(p, q);
                float app = As[dpa];
                float aqq = As[dqa];
                float apq = As[oqa];
                float c = 1.f, s = 0.f, tg = 0.f;
                if (fabsf(apq) > 1e-30f) {
                    float tau = (aqq - app) / (2.0f * apq);
                    tg = 1.0f / (fabsf(tau) + sqrtf(1.0f + tau * tau));
                    if (tau < 0.f) tg = -tg;
                    c = rsqrtf(1.f + tg * tg);
                    s = tg * c;
                }
                cssn[cur][tid] = make_float2(c, s);
                float dpq = tg * apq;
                As[dpa] = app - dpq;
                As[dqa] = aqq + dpq;
                As[oqa] = 0.f;
            }
            // --- S1b: deferred phase 2b of round r-1 (all warps, buf prv) ---
            if (r > 0) {
                const int pqv = pqA[prv][pi2b];
                const int p = pqv & 255, q = pqv >> 8;
                const float2 cs = cssn[prv][pi2b];
                const float c = cs.x, s = cs.y;
                float4* vp = reinterpret_cast<float4*>(&Vt[p * PITCHV + rb2b]);
                float4* vq = reinterpret_cast<float4*>(&Vt[q * PITCHV + rb2b]);
                #pragma unroll
                for (int h = 0; h < 2; ++h) {
                    float4 a = vp[h], b = vq[h];
                    float4 np, nq;
                    np.x = c * a.x - s * b.x;  nq.x = s * a.x + c * b.x;
                    np.y = c * a.y - s * b.y;  nq.y = s * a.y + c * b.y;
                    np.z = c * a.z - s * b.z;  nq.z = s * a.z + c * b.z;
                    np.w = c * a.w - s * b.w;  nq.w = s * a.w + c * b.w;
                    vp[h] = np; vq[h] = nq;
                }
            }
            __syncthreads();

            // --- S2: phase 2a round r: 496 strictly-lower 2x2 blocks ---
            {
                // task 1
                {
                    const int pq1 = pqA[cur][rp1];
                    const int p1 = pq1 & 255, q1 = pq1 >> 8;
                    const float2 cs1 = cssn[cur][rp1];
                    const int pq2 = pqA[cur][cp1];
                    const int p2 = pq2 & 255, q2 = pq2 >> 8;
                    const float2 cs2 = cssn[cur][cp1];
                    const int a00a = max(p1, p2) * PITCH + min(p1, p2);
                    const int a01a = max(p1, q2) * PITCH + min(p1, q2);
                    const int a10a = max(q1, p2) * PITCH + min(q1, p2);
                    const int a11a = max(q1, q2) * PITCH + min(q1, q2);
                    float a00 = As[a00a], a01 = As[a01a];
                    float a10 = As[a10a], a11 = As[a11a];
                    float t00 = cs1.x * a00 - cs1.y * a10;
                    float t01 = cs1.x * a01 - cs1.y * a11;
                    float t10 = cs1.y * a00 + cs1.x * a10;
                    float t11 = cs1.y * a01 + cs1.x * a11;
                    As[a00a] = cs2.x * t00 - cs2.y * t01;
                    As[a01a] = cs2.y * t00 + cs2.x * t01;
                    As[a10a] = cs2.x * t10 - cs2.y * t11;
                    As[a11a] = cs2.y * t10 + cs2.x * t11;
                }
                // task 2 (threads 0..239)
                if (rp2 >= 0) {
                    const int pq1 = pqA[cur][rp2];
                    const int p1 = pq1 & 255, q1 = pq1 >> 8;
                    const float2 cs1 = cssn[cur][rp2];
                    const int pq2 = pqA[cur][cp2];
                    const int p2 = pq2 & 255, q2 = pq2 >> 8;
                    const float2 cs2 = cssn[cur][cp2];
                    const int a00a = max(p1, p2) * PITCH + min(p1, p2);
                    const int a01a = max(p1, q2) * PITCH + min(p1, q2);
                    const int a10a = max(q1, p2) * PITCH + min(q1, p2);
                    const int a11a = max(q1, q2) * PITCH + min(q1, q2);
                    float a00 = As[a00a], a01 = As[a01a];
                    float a10 = As[a10a], a11 = As[a11a];
                    float t00 = cs1.x * a00 - cs1.y * a10;
                    float t01 = cs1.x * a01 - cs1.y * a11;
                    float t10 = cs1.y * a00 + cs1.x * a10;
                    float t11 = cs1.y * a01 + cs1.x * a11;
                    As[a00a] = cs2.x * t00 - cs2.y * t01;
                    As[a01a] = cs2.y * t00 + cs2.x * t01;
                    As[a10a] = cs2.x * t10 - cs2.y * t11;
                    As[a11a] = cs2.y * t10 + cs2.x * t11;
                }
            }
            __syncthreads();
        }

        // ---- flush pending phase 2b of round 62 (buffer 62&1 == 0) ----
        {
            const int pqv = pqA[0][pi2b];
            const int p = pqv & 255, q = pqv >> 8;
            const float2 cs = cssn[0][pi2b];
            const float c = cs.x, s = cs.y;
            float4* vp = reinterpret_cast<float4*>(&Vt[p * PITCHV + rb2b]);
            float4* vq = reinterpret_cast<float4*>(&Vt[q * PITCHV + rb2b]);
            #pragma unroll
            for (int h = 0; h < 2; ++h) {
                float4 a = vp[h], b = vq[h];
                float4 np, nq;
                np.x = c * a.x - s * b.x;  nq.x = s * a.x + c * b.x;
                np.y = c * a.y - s * b.y;  nq.y = s * a.y + c * b.y;
                np.z = c * a.z - s * b.z;  nq.z = s * a.z + c * b.z;
                np.w = c * a.w - s * b.w;  nq.w = s * a.w + c * b.w;
                vp[h] = np; vq[h] = nq;
            }
        }
        __syncthreads();
    }

    // ---- eigenvalue logs ----
    if (tid < 64) ev[tid] = logf(fmaxf(As[tid * PITCH + tid], 1e-12f));
    __syncthreads();

    // ---- logX[i][j] = sum_k (Vt[k][i]*ev[k]) * Vt[k][j]  (fused W) ----
    {
        const int bi = tid >> 4;   // 0..15
        const int bj = tid & 15;   // 0..15
        float acc[4][4];
        #pragma unroll
        for (int u = 0; u < 4; ++u)
            #pragma unroll
            for (int v = 0; v < 4; ++v) acc[u][v] = 0.f;
        for (int k = 0; k < 64; ++k) {
            const float evk = ev[k];
            float4 a = *reinterpret_cast<const float4*>(&Vt[k * PITCHV + 4 * bi]);
            float4 b = *reinterpret_cast<const float4*>(&Vt[k * PITCHV + 4 * bj]);
            float wa[4] = {a.x * evk, a.y * evk, a.z * evk, a.w * evk};
            float vb[4] = {b.x, b.y, b.z, b.w};
            #pragma unroll
            for (int u = 0; u < 4; ++u)
                #pragma unroll
                for (int v = 0; v < 4; ++v) acc[u][v] += wa[u] * vb[v];
        }
        float* outm = out + m * (size_t)NSQ;
        #pragma unroll
        for (int u = 0; u < 4; ++u) {
            float4 o = make_float4(acc[u][0], acc[u][1], acc[u][2], acc[u][3]);
            *reinterpret_cast<float4*>(&outm[(4 * bi + u) * 64 + 4 * bj]) = o;
        }
    }
}

// =====================================================================
// offs[c] = <logP_c, Asym_c>
// =====================================================================
__global__ __launch_bounds__(256) void make_offs_k(const float* __restrict__ LP,
                                                   const float* __restrict__ S,
                                                   float* __restrict__ offs) {
    __shared__ float ws[8];
    int c = blockIdx.x;
    float part = 0.f;
    for (int t = threadIdx.x; t < NSQ; t += 256)
        part += LP[(size_t)c * NSQ + t] * S[(size_t)c * NSQ + t];
    #pragma unroll
    for (int o = 16; o; o >>= 1) part += __shfl_down_sync(0xffffffffu, part, o);
    if ((threadIdx.x & 31) == 0) ws[threadIdx.x >> 5] = part;
    __syncthreads();
    if (threadIdx.x == 0) {
        float s = 0.f;
        #pragma unroll
        for (int w = 0; w < 8; ++w) s += ws[w];
        offs[c] = s;
    }
}

// =====================================================================
// out[n,c] = sum_k logX[n,k] * Asym[c,k] - offs[c]
// Tile: 128 n-rows x 128 classes per block, 256 threads, 8x8 per thread
// =====================================================================
__global__ __launch_bounds__(256) void logits_gemm_k(const float* __restrict__ LX,
                                                     const float* __restrict__ B,
                                                     const float* __restrict__ offs,
                                                     float* __restrict__ out) {
    __shared__ float Xs[128][33];
    __shared__ float Bs[128][33];
    const int tid = threadIdx.x;
    const int n0 = blockIdx.x * 128;
    const int ti = tid >> 4;   // 0..15
    const int tj = tid & 15;   // 0..15

    float acc[8][8];
    #pragma unroll
    for (int u = 0; u < 8; ++u)
        #pragma unroll
        for (int v = 0; v < 8; ++v) acc[u][v] = 0.f;

    for (int k0 = 0; k0 < NSQ; k0 += 32) {
        #pragma unroll
        for (int it = 0; it < 4; ++it) {
            int f = tid + it * 256;          // 0..1023
            int row = f >> 3;
            int c4 = (f & 7) * 4;
            float4 x = *reinterpret_cast<const float4*>(
                &LX[(size_t)(n0 + row) * NSQ + k0 + c4]);
            Xs[row][c4] = x.x; Xs[row][c4 + 1] = x.y;
            Xs[row][c4 + 2] = x.z; Xs[row][c4 + 3] = x.w;
            float4 b = *reinterpret_cast<const float4*>(
                &B[(size_t)row * NSQ + k0 + c4]);
            Bs[row][c4] = b.x; Bs[row][c4 + 1] = b.y;
            Bs[row][c4 + 2] = b.z; Bs[row][c4 + 3] = b.w;
        }
        __syncthreads();

        #pragma unroll 4
        for (int kk = 0; kk < 32; ++kk) {
            float xr[8], bc[8];
            #pragma unroll
            for (int u = 0; u < 8; ++u) xr[u] = Xs[ti + 16 * u][kk];
            #pragma unroll
            for (int v = 0; v < 8; ++v) bc[v] = Bs[tj + 16 * v][kk];
            #pragma unroll
            for (int u = 0; u < 8; ++u)
                #pragma unroll
                for (int v = 0; v < 8; ++v) acc[u][v] += xr[u] * bc[v];
        }
        __syncthreads();
    }

    float offv[8];
    #pragma unroll
    for (int v = 0; v < 8; ++v) offv[v] = offs[tj + 16 * v];
    #pragma unroll
    for (int u = 0; u < 8; ++u) {
        size_t rowoff = (size_t)(n0 + ti + 16 * u) * C_CLS;
        #pragma unroll
        for (int v = 0; v < 8; ++v)
            out[rowoff + tj + 16 * v] = acc[u][v] - offv[v];
    }
}

// =====================================================================
extern "C" void kernel_launch(void* const* d_in, const int* in_sizes, int n_in,
                              void* d_out, int out_size) {
    // inputs in metadata order: X (32768*4096), P (128*4096), A (128*4096)
    const float* X = (const float*)d_in[0];
    const float* P = (const float*)d_in[1];
    const float* A = (const float*)d_in[2];
    if (n_in == 3) {
        int xi = 0;
        for (int i = 1; i < 3; ++i) if (in_sizes[i] > in_sizes[xi]) xi = i;
        if (xi != 0) {
            const float* ins[3] = {(const float*)d_in[0], (const float*)d_in[1],
                                   (const float*)d_in[2]};
            X = ins[xi];
            int k = 0;
            const float* rest[2];
            for (int i = 0; i < 3; ++i) if (i != xi) rest[k++] = ins[i];
            P = rest[0]; A = rest[1];
        }
    }
    float* out = (float*)d_out;

    float *p_logX = nullptr, *p_logP = nullptr, *p_Asym = nullptr, *p_offs = nullptr;
    cudaGetSymbolAddress((void**)&p_logX, g_logX);
    cudaGetSymbolAddress((void**)&p_logP, g_logP);
    cudaGetSymbolAddress((void**)&p_Asym, g_Asym);
    cudaGetSymbolAddress((void**)&p_offs, g_offs);

    make_asym_k<<<C_CLS, 256>>>(A, p_Asym);
    jacobi_logm_k<<<C_CLS, 256>>>(P, p_logP);
    jacobi_logm_k<<<NMAT_X, 256>>>(X, p_logX);
    make_offs_k<<<C_CLS, 256>>>(p_logP, p_Asym, p_offs);
    logits_gemm_k<<<NMAT_X / 128, 256>>>(p_logX, p_Asym, p_offs, out);
}

// round 13
// speedup vs baseline: 1.1696x; 1.0806x over previous
#include <cuda_runtime.h>
#include <math.h>

#define NMAT_X 32768
#define C_CLS  128
#define NDIM   64
#define NSQ    4096          // 64*64
#define PITCH2 66            // even pitch: float2-aligned rows, full-matrix buffers
#define BUFOFF (NDIM * PITCH2)
#define PITCHV 68            // smem pitch for Vt (16B-aligned float4 rows)
#define MAXSWEEP 13

// ---- scratch (device globals; no runtime allocation allowed) ----
__device__ float g_logX[134217728];   // 32768 * 4096  (512 MB)
__device__ float g_logP[C_CLS * NSQ];
__device__ float g_Asym[C_CLS * NSQ];
__device__ float g_offs[C_CLS];

// =====================================================================
// A_sym = tril(A,-1) + tril(A,-1)^T + diag(A)
// =====================================================================
__global__ __launch_bounds__(256) void make_asym_k(const float* __restrict__ A,
                                                   float* __restrict__ S) {
    int c = blockIdx.x;
    const float* Ac = A + (size_t)c * NSQ;
    float* Sc = S + (size_t)c * NSQ;
    for (int t = threadIdx.x; t < NSQ; t += 256) {
        int i = t >> 6, j = t & 63;
        float v;
        if (i == j)      v = Ac[t];
        else if (i > j)  v = Ac[i * 64 + j];
        else             v = Ac[j * 64 + i];
        Sc[t] = v;
    }
}

// =====================================================================
// Brent-Luk systolic Jacobi + logm reconstruction.
// Pairs always at adjacent slots (2k,2k+1); after each round the slots
// are permuted by the fixed ring permutation f (period 63 -> identity
// at sweep boundaries). Permutation fused into write-back, ping-pong A
// buffers. Phase-2a read AND write addresses are per-thread constants.
// Player IDs (for V-column rotation) tracked incrementally via warp
// shuffles in the rotation warp. V in player space, no double buffer.
// =====================================================================
__device__ __forceinline__ int fperm(int s) {
    // slot s occupant moves to slot f(s) for the next round
    if (s == 0) return 0;
    if (s == 1) return 2;
    if (s & 1)  return s - 2;          // odd 3..63 -> s-2
    return (s == 62) ? 63 : s + 2;     // even 2..60 -> s+2 ; 62 -> 63
}

__device__ __forceinline__ void decode_tri(int t, int* rp, int* cp) {
    // t in [0,496): rp in [1,31], cp in [0,rp), t = rp*(rp-1)/2 + cp
    int r = (int)((1.f + sqrtf(8.f * (float)t + 1.f)) * 0.5f);
    while (r * (r - 1) / 2 > t) --r;
    while ((r + 1) * r / 2 <= t) ++r;
    *rp = r;
    *cp = t - r * (r - 1) / 2;
}

__device__ __forceinline__ int canon2(int a, int b) {
    return max(a, b) * PITCH2 + min(a, b);
}

__global__ __launch_bounds__(256, 4) void jacobi_logm_k(const float* __restrict__ in,
                                                        float* __restrict__ out) {
    __shared__ __align__(16) float As[2 * NDIM * PITCH2];
    __shared__ __align__(16) float Vt[NDIM * PITCHV];
    __shared__ float2 cssn[32];
    __shared__ int    pqA[32];
    __shared__ float wsum[8];
    __shared__ float fro2v;
    __shared__ int   convflag;
    __shared__ float ev[64];

    const int tid = threadIdx.x;
    const size_t m = blockIdx.x;
    const float* Xm = in + m * (size_t)NSQ;

    // ---- static task assignment + precomputed offsets (all rounds) ----
    int rp1, cp1, rp2 = -1, cp2 = -1;
    decode_tri(tid, &rp1, &cp1);
    if (tid < 240) decode_tri(tid + 256, &rp2, &cp2);

    // task 1 offsets
    const int rd1a = (2 * rp1) * PITCH2 + 2 * cp1;       // float2 read, row 2ri
    const int rd1b = rd1a + PITCH2;                      // float2 read, row 2ri+1
    const int w100 = canon2(fperm(2 * rp1),     fperm(2 * cp1));
    const int w101 = canon2(fperm(2 * rp1),     fperm(2 * cp1 + 1));
    const int w110 = canon2(fperm(2 * rp1 + 1), fperm(2 * cp1));
    const int w111 = canon2(fperm(2 * rp1 + 1), fperm(2 * cp1 + 1));
    // task 2 offsets
    int rd2a = 0, rd2b = 0, w200 = 0, w201 = 0, w210 = 0, w211 = 0;
    if (rp2 >= 0) {
        rd2a = (2 * rp2) * PITCH2 + 2 * cp2;
        rd2b = rd2a + PITCH2;
        w200 = canon2(fperm(2 * rp2),     fperm(2 * cp2));
        w201 = canon2(fperm(2 * rp2),     fperm(2 * cp2 + 1));
        w210 = canon2(fperm(2 * rp2 + 1), fperm(2 * cp2));
        w211 = canon2(fperm(2 * rp2 + 1), fperm(2 * cp2 + 1));
    }
    // phase-1 static slots (warp 0)
    const int dP  = (2 * tid) * PITCH2 + 2 * tid;            // A[2k][2k]
    const int dQ  = dP + PITCH2 + 1;                         // A[2k+1][2k+1]
    const int dPQ = dP + PITCH2;                             // A[2k+1][2k]
    const int fp_ = fperm(2 * tid), fq_ = fperm(2 * tid + 1);
    const int dPn  = fp_ * PITCH2 + fp_;
    const int dQn  = fq_ * PITCH2 + fq_;
    const int dPQn = canon2(fq_, fp_);
    // player IDs (meaningful in warp 0 only)
    int Pk = 2 * tid, Qk = 2 * tid + 1;
    // phase-2b static assignment
    const int pi2b = tid >> 3;
    const int rb2b = (tid & 7) * 8;

    // ---- load A into buffer 0 (full matrix), init Vt = I, ||A||_F^2 ----
    float part = 0.f;
    for (int t = tid; t < NSQ; t += 256) {
        int i = t >> 6, j = t & 63;
        float v = Xm[t];
        As[i * PITCH2 + j] = v;
        Vt[i * PITCHV + j] = (i == j) ? 1.f : 0.f;
        part += v * v;
    }
    #pragma unroll
    for (int o = 16; o; o >>= 1) part += __shfl_down_sync(0xffffffffu, part, o);
    if ((tid & 31) == 0) wsum[tid >> 5] = part;
    __syncthreads();
    if (tid == 0) {
        float s = 0.f;
        #pragma unroll
        for (int w = 0; w < 8; ++w) s += wsum[w];
        fro2v = s;
        convflag = 0;
    }
    __syncthreads();

    int curoff = 0;

    // ---- Jacobi sweeps ----
    for (int sweep = 0; sweep < MAXSWEEP; ++sweep) {
        if (sweep >= 4) {
            // off-diagonal norm: strictly-lower canonical x2 (current buffer)
            float po = 0.f;
            for (int t = tid; t < NSQ; t += 256) {
                int i = t >> 6, j = t & 63;
                if (i > j) { float v = As[curoff + i * PITCH2 + j]; po += v * v; }
            }
            #pragma unroll
            for (int o = 16; o; o >>= 1) po += __shfl_down_sync(0xffffffffu, po, o);
            if ((tid & 31) == 0) wsum[tid >> 5] = po;
            __syncthreads();
            if (tid == 0) {
                float s = 0.f;
                #pragma unroll
                for (int w = 0; w < 8; ++w) s += wsum[w];
                convflag = (2.f * s <= 1e-10f * fro2v) ? 1 : 0;
            }
            __syncthreads();
            if (convflag) break;
        }

        for (int r = 0; r < 63; ++r) {
            const int newoff = curoff ^ BUFOFF;

            // --- phase 1 (warp 0): rotation params + analytic diagonal ---
            if (tid < 32) {
                pqA[tid] = Pk | (Qk << 8);
                float app = As[curoff + dP];
                float aqq = As[curoff + dQ];
                float apq = As[curoff + dPQ];
                float c = 1.f, s = 0.f, tg = 0.f;
                if (fabsf(apq) > 1e-30f) {
                    float tau = (aqq - app) / (2.0f * apq);
                    tg = 1.0f / (fabsf(tau) + sqrtf(1.0f + tau * tau));
                    if (tau < 0.f) tg = -tg;
                    c = rsqrtf(1.f + tg * tg);
                    s = tg * c;
                }
                cssn[tid] = make_float2(c, s);
                float dpq = tg * apq;
                As[newoff + dPn]  = app - dpq;
                As[newoff + dQn]  = aqq + dpq;
                As[newoff + dPQn] = 0.f;
                // evolve player IDs to next round (round-robin ring)
                int Pprev = __shfl_up_sync(0xffffffffu, Pk, 1);
                int Qnext = __shfl_down_sync(0xffffffffu, Qk, 1);
                int Q0    = __shfl_sync(0xffffffffu, Qk, 0);
                int P31   = __shfl_sync(0xffffffffu, Pk, 31);
                int nP = (tid == 0) ? Pk : ((tid == 1) ? Q0 : Pprev);
                int nQ = (tid == 31) ? P31 : Qnext;
                Pk = nP; Qk = nQ;
            }
            __syncthreads();

            // --- phase 2a: 496 adjacent 2x2 blocks, static addresses ---
            {
                const float2 cs1 = cssn[rp1];
                const float2 cs2 = cssn[cp1];
                float2 ra = *reinterpret_cast<const float2*>(&As[curoff + rd1a]);
                float2 rb = *reinterpret_cast<const float2*>(&As[curoff + rd1b]);
                float t00 = cs1.x * ra.x - cs1.y * rb.x;
                float t01 = cs1.x * ra.y - cs1.y * rb.y;
                float t10 = cs1.y * ra.x + cs1.x * rb.x;
                float t11 = cs1.y * ra.y + cs1.x * rb.y;
                As[newoff + w100] = cs2.x * t00 - cs2.y * t01;
                As[newoff + w101] = cs2.y * t00 + cs2.x * t01;
                As[newoff + w110] = cs2.x * t10 - cs2.y * t11;
                As[newoff + w111] = cs2.y * t10 + cs2.x * t11;
            }
            if (rp2 >= 0) {
                const float2 cs1 = cssn[rp2];
                const float2 cs2 = cssn[cp2];
                float2 ra = *reinterpret_cast<const float2*>(&As[curoff + rd2a]);
                float2 rb = *reinterpret_cast<const float2*>(&As[curoff + rd2b]);
                float t00 = cs1.x * ra.x - cs1.y * rb.x;
                float t01 = cs1.x * ra.y - cs1.y * rb.y;
                float t10 = cs1.y * ra.x + cs1.x * rb.x;
                float t11 = cs1.y * ra.y + cs1.x * rb.y;
                As[newoff + w200] = cs2.x * t00 - cs2.y * t01;
                As[newoff + w201] = cs2.y * t00 + cs2.x * t01;
                As[newoff + w210] = cs2.x * t10 - cs2.y * t11;
                As[newoff + w211] = cs2.y * t10 + cs2.x * t11;
            }
            // --- phase 2b: rotate V player-columns (Vt rows), float4 ---
            {
                const int pqv = pqA[pi2b];
                const int p = pqv & 255, q = pqv >> 8;
                const float2 cs = cssn[pi2b];
                const float c = cs.x, s = cs.y;
                float4* vp = reinterpret_cast<float4*>(&Vt[p * PITCHV + rb2b]);
                float4* vq = reinterpret_cast<float4*>(&Vt[q * PITCHV + rb2b]);
                #pragma unroll
                for (int h = 0; h < 2; ++h) {
                    float4 a = vp[h], b = vq[h];
                    float4 np, nq;
                    np.x = c * a.x - s * b.x;  nq.x = s * a.x + c * b.x;
                    np.y = c * a.y - s * b.y;  nq.y = s * a.y + c * b.y;
                    np.z = c * a.z - s * b.z;  nq.z = s * a.z + c * b.z;
                    np.w = c * a.w - s * b.w;  nq.w = s * a.w + c * b.w;
                    vp[h] = np; vq[h] = nq;
                }
            }
            __syncthreads();
            curoff = newoff;
        }
    }

    // ---- eigenvalue logs (sweep boundary: permutation is identity) ----
    if (tid < 64) ev[tid] = logf(fmaxf(As[curoff + tid * PITCH2 + tid], 1e-12f));
    __syncthreads();

    // ---- logX[i][j] = sum_k (Vt[k][i]*ev[k]) * Vt[k][j]  (fused W) ----
    {
        const int bi = tid >> 4;   // 0..15
        const int bj = tid & 15;   // 0..15
        float acc[4][4];
        #pragma unroll
        for (int u = 0; u < 4; ++u)
            #pragma unroll
            for (int v = 0; v < 4; ++v) acc[u][v] = 0.f;
        for (int k = 0; k < 64; ++k) {
            const float evk = ev[k];
            float4 a = *reinterpret_cast<const float4*>(&Vt[k * PITCHV + 4 * bi]);
            float4 b = *reinterpret_cast<const float4*>(&Vt[k * PITCHV + 4 * bj]);
            float wa[4] = {a.x * evk, a.y * evk, a.z * evk, a.w * evk};
            float vb[4] = {b.x, b.y, b.z, b.w};
            #pragma unroll
            for (int u = 0; u < 4; ++u)
                #pragma unroll
                for (int v = 0; v < 4; ++v) acc[u][v] += wa[u] * vb[v];
        }
        float* outm = out + m * (size_t)NSQ;
        #pragma unroll
        for (int u = 0; u < 4; ++u) {
            float4 o = make_float4(acc[u][0], acc[u][1], acc[u][2], acc[u][3]);
            *reinterpret_cast<float4*>(&outm[(4 * bi + u) * 64 + 4 * bj]) = o;
        }
    }
}

// =====================================================================
// offs[c] = <logP_c, Asym_c>
// =====================================================================
__global__ __launch_bounds__(256) void make_offs_k(const float* __restrict__ LP,
                                                   const float* __restrict__ S,
                                                   float* __restrict__ offs) {
    __shared__ float ws[8];
    int c = blockIdx.x;
    float part = 0.f;
    for (int t = threadIdx.x; t < NSQ; t += 256)
        part += LP[(size_t)c * NSQ + t] * S[(size_t)c * NSQ + t];
    #pragma unroll
    for (int o = 16; o; o >>= 1) part += __shfl_down_sync(0xffffffffu, part, o);
    if ((threadIdx.x & 31) == 0) ws[threadIdx.x >> 5] = part;
    __syncthreads();
    if (threadIdx.x == 0) {
        float s = 0.f;
        #pragma unroll
        for (int w = 0; w < 8; ++w) s += ws[w];
        offs[c] = s;
    }
}

// =====================================================================
// out[n,c] = sum_k logX[n,k] * Asym[c,k] - offs[c]
// Tile: 128 n-rows x 128 classes per block, 256 threads, 8x8 per thread
// =====================================================================
__global__ __launch_bounds__(256) void logits_gemm_k(const float* __restrict__ LX,
                                                     const float* __restrict__ B,
                                                     const float* __restrict__ offs,
                                                     float* __restrict__ out) {
    __shared__ float Xs[128][33];
    __shared__ float Bs[128][33];
    const int tid = threadIdx.x;
    const int n0 = blockIdx.x * 128;
    const int ti = tid >> 4;   // 0..15
    const int tj = tid & 15;   // 0..15

    float acc[8][8];
    #pragma unroll
    for (int u = 0; u < 8; ++u)
        #pragma unroll
        for (int v = 0; v < 8; ++v) acc[u][v] = 0.f;

    for (int k0 = 0; k0 < NSQ; k0 += 32) {
        #pragma unroll
        for (int it = 0; it < 4; ++it) {
            int f = tid + it * 256;          // 0..1023
            int row = f >> 3;
            int c4 = (f & 7) * 4;
            float4 x = *reinterpret_cast<const float4*>(
                &LX[(size_t)(n0 + row) * NSQ + k0 + c4]);
            Xs[row][c4] = x.x; Xs[row][c4 + 1] = x.y;
            Xs[row][c4 + 2] = x.z; Xs[row][c4 + 3] = x.w;
            float4 b = *reinterpret_cast<const float4*>(
                &B[(size_t)row * NSQ + k0 + c4]);
            Bs[row][c4] = b.x; Bs[row][c4 + 1] = b.y;
            Bs[row][c4 + 2] = b.z; Bs[row][c4 + 3] = b.w;
        }
        __syncthreads();

        #pragma unroll 4
        for (int kk = 0; kk < 32; ++kk) {
            float xr[8], bc[8];
            #pragma unroll
            for (int u = 0; u < 8; ++u) xr[u] = Xs[ti + 16 * u][kk];
            #pragma unroll
            for (int v = 0; v < 8; ++v) bc[v] = Bs[tj + 16 * v][kk];
            #pragma unroll
            for (int u = 0; u < 8; ++u)
                #pragma unroll
                for (int v = 0; v < 8; ++v) acc[u][v] += xr[u] * bc[v];
        }
        __syncthreads();
    }

    float offv[8];
    #pragma unroll
    for (int v = 0; v < 8; ++v) offv[v] = offs[tj + 16 * v];
    #pragma unroll
    for (int u = 0; u < 8; ++u) {
        size_t rowoff = (size_t)(n0 + ti + 16 * u) * C_CLS;
        #pragma unroll
        for (int v = 0; v < 8; ++v)
            out[rowoff + tj + 16 * v] = acc[u][v] - offv[v];
    }
}

// =====================================================================
extern "C" void kernel_launch(void* const* d_in, const int* in_sizes, int n_in,
                              void* d_out, int out_size) {
    // inputs in metadata order: X (32768*4096), P (128*4096), A (128*4096)
    const float* X = (const float*)d_in[0];
    const float* P = (const float*)d_in[1];
    const float* A = (const float*)d_in[2];
    if (n_in == 3) {
        int xi = 0;
        for (int i = 1; i < 3; ++i) if (in_sizes[i] > in_sizes[xi]) xi = i;
        if (xi != 0) {
            const float* ins[3] = {(const float*)d_in[0], (const float*)d_in[1],
                                   (const float*)d_in[2]};
            X = ins[xi];
            int k = 0;
            const float* rest[2];
            for (int i = 0; i < 3; ++i) if (i != xi) rest[k++] = ins[i];
            P = rest[0]; A = rest[1];
        }
    }
    float* out = (float*)d_out;

    float *p_logX = nullptr, *p_logP = nullptr, *p_Asym = nullptr, *p_offs = nullptr;
    cudaGetSymbolAddress((void**)&p_logX, g_logX);
    cudaGetSymbolAddress((void**)&p_logP, g_logP);
    cudaGetSymbolAddress((void**)&p_Asym, g_Asym);
    cudaGetSymbolAddress((void**)&p_offs, g_offs);

    make_asym_k<<<C_CLS, 256>>>(A, p_Asym);
    jacobi_logm_k<<<C_CLS, 256>>>(P, p_logP);
    jacobi_logm_k<<<NMAT_X, 256>>>(X, p_logX);
    make_offs_k<<<C_CLS, 256>>>(p_logP, p_Asym, p_offs);
    logits_gemm_k<<<NMAT_X / 128, 256>>>(p_logX, p_Asym, p_offs, out);
}